// round 15
// baseline (speedup 1.0000x reference)
#include <cuda_runtime.h>
#include <cuda_bf16.h>
#include <stdint.h>
#include <math.h>

#define N_ITEMS 100000
#define E1N 400000
#define E2N 400000
#define DIM 128
#define N_TGT 40000

#define ROWB 272           // padded byte stride for 128 bf16 cols (conflict-free LDSM)
#define BTILE (128 * ROWB) // 34816 bytes per 128x128 bf16 tile

// ---------------- scratch (static device globals; no runtime allocation) ----------------
__device__ float d_ft[(size_t)N_ITEMS * DIM];   // aggregated item features
__device__ float d_g [(size_t)N_ITEMS * DIM];   // ft @ W_q[:128]   (fp32 — bf16 fails rel_err)
__device__ float d_f [(size_t)N_TGT  * DIM];    // concat(h_t,last) @ W_r (fp32)
__device__ float d_e1[E1N];
__device__ float d_ex[E1N];
__device__ int   d_menc[N_ITEMS];
__device__ float d_z [N_ITEMS];
// prepped bf16 hi/lo weight tiles, [n][k] ROWB-padded:
__device__ __align__(16) unsigned char d_BhT[BTILE];  // W_q[0:128]^T   (gemm_g)
__device__ __align__(16) unsigned char d_BlT[BTILE];
__device__ __align__(16) unsigned char d_Bh2[BTILE];  // W_q[128:256]^T (edge2)
__device__ __align__(16) unsigned char d_Bl2[BTILE];
__device__ __align__(16) unsigned char d_BhR0[BTILE]; // W_r[0:128]^T   (gemm_f)
__device__ __align__(16) unsigned char d_BlR0[BTILE];
__device__ __align__(16) unsigned char d_BhR1[BTILE]; // W_r[128:256]^T (gemm_f)
__device__ __align__(16) unsigned char d_BlR1[BTILE];

// ---------------- helpers ----------------
__device__ __forceinline__ int fenc(float f) {
    int i = __float_as_int(f);
    return (i >= 0) ? i : (i ^ 0x7FFFFFFF);
}
__device__ __forceinline__ float fdec(int i) {
    return __int_as_float((i >= 0) ? i : (i ^ 0x7FFFFFFF));
}
__device__ __forceinline__ void red_add_v4(float* p, float4 v) {
    asm volatile("red.global.add.v4.f32 [%0], {%1, %2, %3, %4};"
                 :: "l"(p), "f"(v.x), "f"(v.y), "f"(v.z), "f"(v.w) : "memory");
}
__device__ __forceinline__ uint32_t smem_to_u32(const void* p) {
    uint32_t a;
    asm("{ .reg .u64 t; cvta.to.shared.u64 t, %1; cvt.u32.u64 %0, t; }" : "=r"(a) : "l"(p));
    return a;
}
__device__ __forceinline__ float tanh_fast(float x) {
    float r;
    asm("tanh.approx.f32 %0, %1;" : "=f"(r) : "f"(x));
    return r;
}
__device__ __forceinline__ void ldsm_x4(uint32_t &r0, uint32_t &r1, uint32_t &r2, uint32_t &r3, uint32_t addr) {
    asm volatile("ldmatrix.sync.aligned.m8n8.x4.shared.b16 {%0,%1,%2,%3}, [%4];"
                 : "=r"(r0), "=r"(r1), "=r"(r2), "=r"(r3) : "r"(addr));
}
__device__ __forceinline__ void mma_bf16(float &d0, float &d1, float &d2, float &d3,
                                         uint32_t a0, uint32_t a1, uint32_t a2, uint32_t a3,
                                         uint32_t b0, uint32_t b1) {
    asm volatile("mma.sync.aligned.m16n8k16.row.col.f32.bf16.bf16.f32 "
                 "{%0,%1,%2,%3}, {%4,%5,%6,%7}, {%8,%9}, {%0,%1,%2,%3};"
                 : "+f"(d0), "+f"(d1), "+f"(d2), "+f"(d3)
                 : "r"(a0), "r"(a1), "r"(a2), "r"(a3), "r"(b0), "r"(b1));
}
// split float2 -> bf16x2 hi + bf16x2 lo (residual)
__device__ __forceinline__ void split2(float2 v, uint32_t &hi, uint32_t &lo) {
    __nv_bfloat16 hx = __float2bfloat16(v.x);
    __nv_bfloat16 hy = __float2bfloat16(v.y);
    __nv_bfloat162 hp; hp.x = hx; hp.y = hy;
    __nv_bfloat162 lp = __floats2bfloat162_rn(v.x - __bfloat162float(hx),
                                              v.y - __bfloat162float(hy));
    hi = *(uint32_t*)&hp;
    lo = *(uint32_t*)&lp;
}

// 3-term split-mma over one k16 x 128-N strip (full-width kernels: gemm_g/gemm_f)
#define MMA_STRIP(koff)                                                                        \
    _Pragma("unroll")                                                                          \
    for (int nt = 0; nt < 8; nt++) {                                                           \
        uint32_t noff = (uint32_t)nt * (16 * ROWB) + (koff);                                   \
        uint32_t bh0, bh1, bh2, bh3, bl0, bl1, bl2, bl3;                                       \
        ldsm_x4(bh0, bh1, bh2, bh3, bh_base + noff);                                           \
        ldsm_x4(bl0, bl1, bl2, bl3, bl_base + noff);                                           \
        int t0 = nt * 2, t1 = nt * 2 + 1;                                                      \
        mma_bf16(acc[t0][0], acc[t0][1], acc[t0][2], acc[t0][3], ah0, ah1, ah2, ah3, bh0, bh1);\
        mma_bf16(acc[t1][0], acc[t1][1], acc[t1][2], acc[t1][3], ah0, ah1, ah2, ah3, bh2, bh3);\
        mma_bf16(acc[t0][0], acc[t0][1], acc[t0][2], acc[t0][3], ah0, ah1, ah2, ah3, bl0, bl1);\
        mma_bf16(acc[t1][0], acc[t1][1], acc[t1][2], acc[t1][3], ah0, ah1, ah2, ah3, bl2, bl3);\
        mma_bf16(acc[t0][0], acc[t0][1], acc[t0][2], acc[t0][3], al0, al1, al2, al3, bh0, bh1);\
        mma_bf16(acc[t1][0], acc[t1][1], acc[t1][2], acc[t1][3], al0, al1, al2, al3, bh2, bh3);\
    }

#define SPLIT_FRAGS(v00, v10, v01, v11)                                                        \
    uint32_t ah0, ah1, ah2, ah3, al0, al1, al2, al3;                                           \
    split2(v00, ah0, al0);                                                                     \
    split2(v10, ah1, al1);                                                                     \
    split2(v01, ah2, al2);                                                                     \
    split2(v11, ah3, al3);

// ---------------- K0: init accumulators ----------------
__global__ void init_kernel(float* __restrict__ out) {
    int stride = gridDim.x * blockDim.x;
    int i0 = blockIdx.x * blockDim.x + threadIdx.x;
    for (int i = i0; i < N_ITEMS * DIM; i += stride) d_ft[i] = 0.0f;
    for (int i = i0; i < N_TGT * DIM;  i += stride) out[i]  = 0.0f;
    for (int i = i0; i < N_ITEMS;      i += stride) { d_z[i] = 0.0f; d_menc[i] = (int)0x80000000; }
}

// ---------------- prep: bf16 hi/lo transposed tiles of W_q (both halves) ----------------
__global__ void prep_wq_kernel(const float* __restrict__ W_q) {
    int i = blockIdx.x * blockDim.x + threadIdx.x;
    if (i >= 2 * DIM * DIM) return;
    int half = i >> 14;
    int j = i & 16383;
    int n = j >> 7, k = j & 127;
    float w = W_q[(size_t)(half * DIM + k) * DIM + n];
    __nv_bfloat16 hi = __float2bfloat16(w);
    __nv_bfloat16 lo = __float2bfloat16(w - __bfloat162float(hi));
    uint32_t off = (uint32_t)n * ROWB + k * 2;
    unsigned char* bh = half ? d_Bh2 : d_BhT;
    unsigned char* bl = half ? d_Bl2 : d_BlT;
    *(__nv_bfloat16*)(bh + off) = hi;
    *(__nv_bfloat16*)(bl + off) = lo;
}

// ---------------- prep: bf16 hi/lo transposed tiles of W_r (both halves) ----------------
__global__ void prep_wr_kernel(const float* __restrict__ W_r) {
    int i = blockIdx.x * blockDim.x + threadIdx.x;
    if (i >= 2 * DIM * DIM) return;
    int half = i >> 14;
    int j = i & 16383;
    int n = j >> 7, k = j & 127;
    float w = W_r[(size_t)(half * DIM + k) * DIM + n];
    __nv_bfloat16 hi = __float2bfloat16(w);
    __nv_bfloat16 lo = __float2bfloat16(w - __bfloat162float(hi));
    uint32_t off = (uint32_t)n * ROWB + k * 2;
    unsigned char* bh = half ? d_BhR1 : d_BhR0;
    unsigned char* bl = half ? d_BlR1 : d_BlR0;
    *(__nv_bfloat16*)(bh + off) = hi;
    *(__nv_bfloat16*)(bl + off) = lo;
}

// ---------------- K1: per-edge logit + segment max (4 edges per warp) ----------------
__global__ __launch_bounds__(256) void edge1_kernel(
    const float* __restrict__ h_v, const float* __restrict__ h_d,
    const float* __restrict__ W_pi, const float* __restrict__ W_M,
    const int* __restrict__ src1, const int* __restrict__ dst1)
{
    int warp = blockIdx.x * 8 + (threadIdx.x >> 5);
    int lane = threadIdx.x & 31;
    int e0 = warp * 4;
    float4 p  = ((const float4*)W_pi)[lane];
    float4 ma = ((const float4*)W_M)[lane];
    float4 mb = ((const float4*)(W_M + DIM))[lane];
    int s[4], d[4];
    #pragma unroll
    for (int i = 0; i < 4; i++) { s[i] = src1[e0 + i]; d[i] = dst1[e0 + i]; }
    float4 a[4], b[4], hh[4];
    #pragma unroll
    for (int i = 0; i < 4; i++) {
        a[i]  = ((const float4*)(h_v + (size_t)s[i] * DIM))[lane];
        b[i]  = ((const float4*)(h_v + (size_t)d[i] * DIM))[lane];
        hh[i] = __ldcs(((const float4*)(h_d + (size_t)(e0 + i) * DIM)) + lane);
    }
    float ev[4], mv[4];
    #pragma unroll
    for (int i = 0; i < 4; i++) {
        float4 uv = make_float4(a[i].x*b[i].x, a[i].y*b[i].y, a[i].z*b[i].z, a[i].w*b[i].w);
        ev[i] = uv.x*hh[i].x*p.x + uv.y*hh[i].y*p.y + uv.z*hh[i].z*p.z + uv.w*hh[i].w*p.w;
        mv[i] = uv.x*ma.x + uv.y*ma.y + uv.z*ma.z + uv.w*ma.w
              + hh[i].x*mb.x + hh[i].y*mb.y + hh[i].z*mb.z + hh[i].w*mb.w;
    }
    #pragma unroll
    for (int o = 16; o; o >>= 1) {
        #pragma unroll
        for (int i = 0; i < 4; i++) {
            ev[i] += __shfl_xor_sync(0xffffffffu, ev[i], o);
            mv[i] += __shfl_xor_sync(0xffffffffu, mv[i], o);
        }
    }
    if (lane == 0) {
        #pragma unroll
        for (int i = 0; i < 4; i++) {
            float e = ev[i] * (1.0f / (1.0f + expf(-mv[i])));
            d_e1[e0 + i] = e;
            atomicMax(&d_menc[d[i]], fenc(e));
        }
    }
}

// ---------------- K2: exp + segment sum (thread per edge) ----------------
__global__ void edge1_softmax_kernel(const int* __restrict__ dst1) {
    int e = blockIdx.x * blockDim.x + threadIdx.x;
    if (e >= E1N) return;
    int d = dst1[e];
    float m = fdec(d_menc[d]);
    float v = expf(d_e1[e] - m);
    d_ex[e] = v;
    atomicAdd(&d_z[d], v);
}

// ---------------- K3: normalize + aggregate ft (4 edges per warp) ----------------
__global__ __launch_bounds__(256) void edge1_agg_kernel(
    const float* __restrict__ h_v,
    const int* __restrict__ src1, const int* __restrict__ dst1)
{
    int warp = blockIdx.x * 8 + (threadIdx.x >> 5);
    int lane = threadIdx.x & 31;
    int e0 = warp * 4;
    int s[4], d[4];
    #pragma unroll
    for (int i = 0; i < 4; i++) { s[i] = src1[e0 + i]; d[i] = dst1[e0 + i]; }
    float a[4];
    #pragma unroll
    for (int i = 0; i < 4; i++) a[i] = d_ex[e0 + i] / d_z[d[i]];
    float4 v[4];
    #pragma unroll
    for (int i = 0; i < 4; i++) v[i] = ((const float4*)(h_v + (size_t)s[i] * DIM))[lane];
    #pragma unroll
    for (int i = 0; i < 4; i++) {
        v[i].x *= a[i]; v[i].y *= a[i]; v[i].z *= a[i]; v[i].w *= a[i];
        red_add_v4(d_ft + (size_t)d[i] * DIM + lane * 4, v[i]);
    }
}

// ---------------- K4: g = ft @ W_q[:128]  (mma.sync bf16-split, pipelined A) ----------------
#define SMG_TOTAL (2 * BTILE)
__global__ __launch_bounds__(256, 2) void gemm_g_mma() {
    extern __shared__ __align__(16) char smem[];
    uint32_t sb = smem_to_u32(smem);
    int tid = threadIdx.x;
    int w = tid >> 5;
    int lane = tid & 31;

    {
        const float4* gh = (const float4*)d_BhT;
        const float4* gl = (const float4*)d_BlT;
        float4* sh = (float4*)smem;
        float4* sl = (float4*)(smem + BTILE);
        for (int i = tid; i < BTILE / 16; i += 256) { sh[i] = gh[i]; sl[i] = gl[i]; }
    }
    __syncthreads();

    float acc[16][4];
    #pragma unroll
    for (int t = 0; t < 16; t++)
        #pragma unroll
        for (int j = 0; j < 4; j++) acc[t][j] = 0.0f;

    int qi = lane & 7;
    int quad = lane >> 3;
    uint32_t b_lane = (uint32_t)(qi + ((quad >= 2) ? 8 : 0)) * ROWB + ((quad & 1) ? 16 : 0);
    uint32_t bh_base = sb + b_lane;
    uint32_t bl_base = sb + BTILE + b_lane;

    int row0 = blockIdx.x * 128 + w * 16 + (lane >> 2);
    int row1 = row0 + 8;
    int r0c = (row0 < N_ITEMS) ? row0 : (N_ITEMS - 1);
    int r1c = (row1 < N_ITEMS) ? row1 : (N_ITEMS - 1);
    const float* pa = d_ft + (size_t)r0c * DIM;
    const float* pb = d_ft + (size_t)r1c * DIM;
    int c0 = (lane & 3) * 2;

    float2 n00 = *(const float2*)(pa + c0);
    float2 n10 = *(const float2*)(pb + c0);
    float2 n01 = *(const float2*)(pa + c0 + 8);
    float2 n11 = *(const float2*)(pb + c0 + 8);
    #pragma unroll
    for (int k16 = 0; k16 < 8; k16++) {
        float2 v00 = n00, v10 = n10, v01 = n01, v11 = n11;
        if (k16 < 7) {
            int kb = (k16 + 1) * 16 + c0;
            n00 = *(const float2*)(pa + kb);
            n10 = *(const float2*)(pb + kb);
            n01 = *(const float2*)(pa + kb + 8);
            n11 = *(const float2*)(pb + kb + 8);
        }
        SPLIT_FRAGS(v00, v10, v01, v11);
        MMA_STRIP((uint32_t)k16 * 32);
    }

    #pragma unroll
    for (int t = 0; t < 16; t++) {
        int n = t * 8 + c0;
        if (row0 < N_ITEMS) *(float2*)&d_g[(size_t)row0 * DIM + n] = make_float2(acc[t][0], acc[t][1]);
        if (row1 < N_ITEMS) *(float2*)&d_g[(size_t)row1 * DIM + n] = make_float2(acc[t][2], acc[t][3]);
    }
}

// ---------------- K5: f = concat(h_t, ft[last]) @ W_r  (mma.sync, 2-phase K) ----------------
__global__ __launch_bounds__(256, 2) void gemm_f_mma(
    const float* __restrict__ h_t, const int* __restrict__ last_idx)
{
    extern __shared__ __align__(16) char smem[];
    uint32_t sb = smem_to_u32(smem);
    int tid = threadIdx.x;
    int w = tid >> 5;
    int lane = tid & 31;

    float acc[16][4];
    #pragma unroll
    for (int t = 0; t < 16; t++)
        #pragma unroll
        for (int j = 0; j < 4; j++) acc[t][j] = 0.0f;

    int qi = lane & 7;
    int quad = lane >> 3;
    uint32_t b_lane = (uint32_t)(qi + ((quad >= 2) ? 8 : 0)) * ROWB + ((quad & 1) ? 16 : 0);
    uint32_t bh_base = sb + b_lane;
    uint32_t bl_base = sb + BTILE + b_lane;

    int row0 = blockIdx.x * 128 + w * 16 + (lane >> 2);
    int row1 = row0 + 8;
    int r0c = (row0 < N_TGT) ? row0 : (N_TGT - 1);
    int r1c = (row1 < N_TGT) ? row1 : (N_TGT - 1);
    int c0 = (lane & 3) * 2;

    // phase 0: B = W_r[0:128]^T, A = h_t
    {
        const float4* gh = (const float4*)d_BhR0;
        const float4* gl = (const float4*)d_BlR0;
        float4* sh = (float4*)smem;
        float4* sl = (float4*)(smem + BTILE);
        for (int i = tid; i < BTILE / 16; i += 256) { sh[i] = gh[i]; sl[i] = gl[i]; }
    }
    __syncthreads();
    {
        const float* pa = h_t + (size_t)r0c * DIM;
        const float* pb = h_t + (size_t)r1c * DIM;
        #pragma unroll
        for (int k16 = 0; k16 < 8; k16++) {
            float2 v00 = *(const float2*)(pa + k16 * 16 + c0);
            float2 v10 = *(const float2*)(pb + k16 * 16 + c0);
            float2 v01 = *(const float2*)(pa + k16 * 16 + c0 + 8);
            float2 v11 = *(const float2*)(pb + k16 * 16 + c0 + 8);
            SPLIT_FRAGS(v00, v10, v01, v11);
            MMA_STRIP((uint32_t)k16 * 32);
        }
    }
    __syncthreads();

    // phase 1: B = W_r[128:256]^T, A = ft[last_idx[row/4]]
    {
        const float4* gh = (const float4*)d_BhR1;
        const float4* gl = (const float4*)d_BlR1;
        float4* sh = (float4*)smem;
        float4* sl = (float4*)(smem + BTILE);
        for (int i = tid; i < BTILE / 16; i += 256) { sh[i] = gh[i]; sl[i] = gl[i]; }
    }
    __syncthreads();
    {
        const float* pa = d_ft + (size_t)last_idx[r0c >> 2] * DIM;
        const float* pb = d_ft + (size_t)last_idx[r1c >> 2] * DIM;
        #pragma unroll
        for (int k16 = 0; k16 < 8; k16++) {
            float2 v00 = *(const float2*)(pa + k16 * 16 + c0);
            float2 v10 = *(const float2*)(pb + k16 * 16 + c0);
            float2 v01 = *(const float2*)(pa + k16 * 16 + c0 + 8);
            float2 v11 = *(const float2*)(pb + k16 * 16 + c0 + 8);
            SPLIT_FRAGS(v00, v10, v01, v11);
            MMA_STRIP((uint32_t)k16 * 32);
        }
    }

    #pragma unroll
    for (int t = 0; t < 16; t++) {
        int n = t * 8 + c0;
        if (row0 < N_TGT) *(float2*)&d_f[(size_t)row0 * DIM + n] = make_float2(acc[t][0], acc[t][1]);
        if (row1 < N_TGT) *(float2*)&d_f[(size_t)row1 * DIM + n] = make_float2(acc[t][2], acc[t][3]);
    }
}

// ---------------- K6: edge2 — N split in two 64-halves (acc 32 regs), occupancy 3 ----------------
#define SM_BH   0
#define SM_BL   BTILE
#define SM_SRC  (2 * BTILE)
#define SM_DST  (SM_SRC + 512)
#define SM_S    (SM_DST + 512)
#define SM_TOTAL (SM_S + 512)

__global__ __launch_bounds__(256, 3)
void edge2_mma_kernel(
    const float* __restrict__ h_p,
    const int* __restrict__ src2, const int* __restrict__ dst2,
    float* __restrict__ out)
{
    extern __shared__ __align__(16) char smem[];
    uint32_t sb = smem_to_u32(smem);
    int tid = threadIdx.x;
    int w = tid >> 5;
    int lane = tid & 31;

    int* ssrc = (int*)(smem + SM_SRC);
    int* sdst = (int*)(smem + SM_DST);
    float* s_s = (float*)(smem + SM_S);

    // B tiles once per block (reused by both edge tiles and both halves)
    {
        const float4* gh = (const float4*)d_Bh2;
        const float4* gl = (const float4*)d_Bl2;
        float4* sh = (float4*)(smem + SM_BH);
        float4* sl = (float4*)(smem + SM_BL);
        for (int i = tid; i < BTILE / 16; i += 256) { sh[i] = gh[i]; sl[i] = gl[i]; }
    }

    int qi = lane & 7;
    int quad = lane >> 3;
    uint32_t b_lane = (uint32_t)(qi + ((quad >= 2) ? 8 : 0)) * ROWB + ((quad & 1) ? 16 : 0);
    uint32_t bh_base = sb + SM_BH + b_lane;
    uint32_t bl_base = sb + SM_BL + b_lane;
    int c0 = (lane & 3) * 2;

    for (int tile = 0; tile < 2; tile++) {
        int eb = blockIdx.x * 256 + tile * 128;
        if (eb >= E2N) break;

        if (tid < 128) { ssrc[tid] = src2[eb + tid]; sdst[tid] = dst2[eb + tid]; }
        __syncthreads();

        int r0 = w * 16 + (lane >> 2);
        int r1 = r0 + 8;
        const float* pa = h_p + (size_t)(eb + r0) * DIM;
        const float* pb = pa + 8 * DIM;

        float s0 = 0.0f, s1 = 0.0f;

        #pragma unroll
        for (int half = 0; half < 2; half++) {
            float acc[8][4];
            #pragma unroll
            for (int t = 0; t < 8; t++)
                #pragma unroll
                for (int j = 0; j < 4; j++) acc[t][j] = 0.0f;

            // mainloop over K, N restricted to this 64-wide half
            #pragma unroll
            for (int k16 = 0; k16 < 8; k16++) {
                int kb = k16 * 16 + c0;
                float2 v00 = *(const float2*)(pa + kb);
                float2 v10 = *(const float2*)(pb + kb);
                float2 v01 = *(const float2*)(pa + kb + 8);
                float2 v11 = *(const float2*)(pb + kb + 8);
                SPLIT_FRAGS(v00, v10, v01, v11);
                uint32_t koff = (uint32_t)k16 * 32;
                #pragma unroll
                for (int nt = 0; nt < 4; nt++) {
                    uint32_t noff = (uint32_t)(half * 4 + nt) * (16 * ROWB) + koff;
                    uint32_t bh0, bh1, bh2, bh3, bl0, bl1, bl2, bl3;
                    ldsm_x4(bh0, bh1, bh2, bh3, bh_base + noff);
                    ldsm_x4(bl0, bl1, bl2, bl3, bl_base + noff);
                    int t0 = nt * 2, t1 = nt * 2 + 1;
                    mma_bf16(acc[t0][0], acc[t0][1], acc[t0][2], acc[t0][3], ah0, ah1, ah2, ah3, bh0, bh1);
                    mma_bf16(acc[t1][0], acc[t1][1], acc[t1][2], acc[t1][3], ah0, ah1, ah2, ah3, bh2, bh3);
                    mma_bf16(acc[t0][0], acc[t0][1], acc[t0][2], acc[t0][3], ah0, ah1, ah2, ah3, bl0, bl1);
                    mma_bf16(acc[t1][0], acc[t1][1], acc[t1][2], acc[t1][3], ah0, ah1, ah2, ah3, bl2, bl3);
                    mma_bf16(acc[t0][0], acc[t0][1], acc[t0][2], acc[t0][3], al0, al1, al2, al3, bh0, bh1);
                    mma_bf16(acc[t1][0], acc[t1][1], acc[t1][2], acc[t1][3], al0, al1, al2, al3, bh2, bh3);
                }
            }

            // partial epilogue for this half: s += sum over n in [half*64, half*64+64)
            {
                const float* g0p = d_g + (size_t)ssrc[r0] * DIM;
                const float* f0p = d_f + (size_t)sdst[r0] * DIM;
                const float* g1p = d_g + (size_t)ssrc[r1] * DIM;
                const float* f1p = d_f + (size_t)sdst[r1] * DIM;
                #pragma unroll
                for (int t = 0; t < 8; t++) {
                    int n = half * 64 + t * 8 + c0;
                    float2 ga = *(const float2*)(g0p + n);
                    float2 fa = *(const float2*)(f0p + n);
                    float2 gb = *(const float2*)(g1p + n);
                    float2 fb = *(const float2*)(f1p + n);
                    s0 += tanh_fast(acc[t][0] + ga.x) * fa.x + tanh_fast(acc[t][1] + ga.y) * fa.y;
                    s1 += tanh_fast(acc[t][2] + gb.x) * fb.x + tanh_fast(acc[t][3] + gb.y) * fb.y;
                }
            }
        }

        s0 += __shfl_xor_sync(0xffffffffu, s0, 1);
        s0 += __shfl_xor_sync(0xffffffffu, s0, 2);
        s1 += __shfl_xor_sync(0xffffffffu, s1, 1);
        s1 += __shfl_xor_sync(0xffffffffu, s1, 2);
        if ((lane & 3) == 0) { s_s[r0] = s0; s_s[r1] = s1; }
        __syncthreads();

        // scatter: out[dst2[e]] += ft[src2[e]] * s[e]
        {
            #pragma unroll 4
            for (int r = w * 16; r < w * 16 + 16; r++) {
                float sv = s_s[r];
                float4 v = ((const float4*)(d_ft + (size_t)ssrc[r] * DIM))[lane];
                v.x *= sv; v.y *= sv; v.z *= sv; v.w *= sv;
                red_add_v4(out + (size_t)sdst[r] * DIM + lane * 4, v);
            }
        }
        __syncthreads();
    }
}

// ---------------- launcher ----------------
extern "C" void kernel_launch(void* const* d_in, const int* in_sizes, int n_in,
                              void* d_out, int out_size) {
    const float* h_v  = (const float*)d_in[0];
    const float* h_d  = (const float*)d_in[1];
    const float* h_p  = (const float*)d_in[2];
    const float* h_t  = (const float*)d_in[3];
    const float* W_pi = (const float*)d_in[4];
    const float* W_M  = (const float*)d_in[5];
    const float* W_q  = (const float*)d_in[6];
    const float* W_r  = (const float*)d_in[7];
    const int* src1 = (const int*)d_in[8];
    const int* dst1 = (const int*)d_in[9];
    const int* src2 = (const int*)d_in[10];
    const int* dst2 = (const int*)d_in[11];
    const int* last_idx = (const int*)d_in[12];
    float* out = (float*)d_out;

    cudaFuncSetAttribute(edge2_mma_kernel, cudaFuncAttributeMaxDynamicSharedMemorySize, SM_TOTAL);
    cudaFuncSetAttribute(gemm_g_mma, cudaFuncAttributeMaxDynamicSharedMemorySize, SMG_TOTAL);
    cudaFuncSetAttribute(gemm_f_mma, cudaFuncAttributeMaxDynamicSharedMemorySize, SMG_TOTAL);

    init_kernel<<<2048, 256>>>(out);                          // 0
    prep_wq_kernel<<<(2 * DIM * DIM + 255) / 256, 256>>>(W_q); // 1
    prep_wr_kernel<<<(2 * DIM * DIM + 255) / 256, 256>>>(W_r); // 2
    edge1_kernel<<<E1N / 32, 256>>>(h_v, h_d, W_pi, W_M, src1, dst1); // 3 <- profiled
    edge1_softmax_kernel<<<(E1N + 255) / 256, 256>>>(dst1);   // 4
    edge1_agg_kernel<<<E1N / 32, 256>>>(h_v, src1, dst1);     // 5
    gemm_g_mma<<<(N_ITEMS + 127) / 128, 256, SMG_TOTAL>>>();  // 6
    gemm_f_mma<<<(N_TGT + 127) / 128, 256, SMG_TOTAL>>>(h_t, last_idx); // 7
    edge2_mma_kernel<<<(E2N + 255) / 256, 256, SM_TOTAL>>>(h_p, src2, dst2, out); // 8
}

// round 17
// speedup vs baseline: 1.4755x; 1.4755x over previous
#include <cuda_runtime.h>
#include <cuda_bf16.h>
#include <stdint.h>
#include <math.h>

#define N_ITEMS 100000
#define E1N 400000
#define E2N 400000
#define DIM 128
#define N_TGT 40000

#define ROWB 272           // padded byte stride for 128 bf16 cols (conflict-free LDSM)
#define BTILE (128 * ROWB) // 34816 bytes per 128x128 bf16 tile

// ---------------- scratch (static device globals; no runtime allocation) ----------------
__device__ float d_ft[(size_t)N_ITEMS * DIM];   // aggregated item features
__device__ float d_g [(size_t)N_ITEMS * DIM];   // ft @ W_q[:128]   (fp32 — bf16 fails rel_err)
__device__ float d_f [(size_t)N_TGT  * DIM];    // concat(h_t,last) @ W_r (fp32)
__device__ float d_s [E2N];                     // per-edge rowdot scalar (edge2 fission)
__device__ float d_e1[E1N];
__device__ float d_ex[E1N];
__device__ int   d_menc[N_ITEMS];
__device__ float d_z [N_ITEMS];
// prepped bf16 hi/lo weight tiles, [n][k] ROWB-padded:
__device__ __align__(16) unsigned char d_BhT[BTILE];  // W_q[0:128]^T   (gemm_g)
__device__ __align__(16) unsigned char d_BlT[BTILE];
__device__ __align__(16) unsigned char d_Bh2[BTILE];  // W_q[128:256]^T (edge2)
__device__ __align__(16) unsigned char d_Bl2[BTILE];
__device__ __align__(16) unsigned char d_BhR0[BTILE]; // W_r[0:128]^T   (gemm_f)
__device__ __align__(16) unsigned char d_BlR0[BTILE];
__device__ __align__(16) unsigned char d_BhR1[BTILE]; // W_r[128:256]^T (gemm_f)
__device__ __align__(16) unsigned char d_BlR1[BTILE];

// ---------------- helpers ----------------
__device__ __forceinline__ int fenc(float f) {
    int i = __float_as_int(f);
    return (i >= 0) ? i : (i ^ 0x7FFFFFFF);
}
__device__ __forceinline__ float fdec(int i) {
    return __int_as_float((i >= 0) ? i : (i ^ 0x7FFFFFFF));
}
__device__ __forceinline__ void red_add_v4(float* p, float4 v) {
    asm volatile("red.global.add.v4.f32 [%0], {%1, %2, %3, %4};"
                 :: "l"(p), "f"(v.x), "f"(v.y), "f"(v.z), "f"(v.w) : "memory");
}
__device__ __forceinline__ uint32_t smem_to_u32(const void* p) {
    uint32_t a;
    asm("{ .reg .u64 t; cvta.to.shared.u64 t, %1; cvt.u32.u64 %0, t; }" : "=r"(a) : "l"(p));
    return a;
}
__device__ __forceinline__ float tanh_fast(float x) {
    float r;
    asm("tanh.approx.f32 %0, %1;" : "=f"(r) : "f"(x));
    return r;
}
__device__ __forceinline__ void ldsm_x4(uint32_t &r0, uint32_t &r1, uint32_t &r2, uint32_t &r3, uint32_t addr) {
    asm volatile("ldmatrix.sync.aligned.m8n8.x4.shared.b16 {%0,%1,%2,%3}, [%4];"
                 : "=r"(r0), "=r"(r1), "=r"(r2), "=r"(r3) : "r"(addr));
}
__device__ __forceinline__ void mma_bf16(float &d0, float &d1, float &d2, float &d3,
                                         uint32_t a0, uint32_t a1, uint32_t a2, uint32_t a3,
                                         uint32_t b0, uint32_t b1) {
    asm volatile("mma.sync.aligned.m16n8k16.row.col.f32.bf16.bf16.f32 "
                 "{%0,%1,%2,%3}, {%4,%5,%6,%7}, {%8,%9}, {%0,%1,%2,%3};"
                 : "+f"(d0), "+f"(d1), "+f"(d2), "+f"(d3)
                 : "r"(a0), "r"(a1), "r"(a2), "r"(a3), "r"(b0), "r"(b1));
}
// split float2 -> bf16x2 hi + bf16x2 lo (residual)
__device__ __forceinline__ void split2(float2 v, uint32_t &hi, uint32_t &lo) {
    __nv_bfloat16 hx = __float2bfloat16(v.x);
    __nv_bfloat16 hy = __float2bfloat16(v.y);
    __nv_bfloat162 hp; hp.x = hx; hp.y = hy;
    __nv_bfloat162 lp = __floats2bfloat162_rn(v.x - __bfloat162float(hx),
                                              v.y - __bfloat162float(hy));
    hi = *(uint32_t*)&hp;
    lo = *(uint32_t*)&lp;
}

// 3-term split-mma over one k16 x 128-N strip
#define MMA_STRIP(koff)                                                                        \
    _Pragma("unroll")                                                                          \
    for (int nt = 0; nt < 8; nt++) {                                                           \
        uint32_t noff = (uint32_t)nt * (16 * ROWB) + (koff);                                   \
        uint32_t bh0, bh1, bh2, bh3, bl0, bl1, bl2, bl3;                                       \
        ldsm_x4(bh0, bh1, bh2, bh3, bh_base + noff);                                           \
        ldsm_x4(bl0, bl1, bl2, bl3, bl_base + noff);                                           \
        int t0 = nt * 2, t1 = nt * 2 + 1;                                                      \
        mma_bf16(acc[t0][0], acc[t0][1], acc[t0][2], acc[t0][3], ah0, ah1, ah2, ah3, bh0, bh1);\
        mma_bf16(acc[t1][0], acc[t1][1], acc[t1][2], acc[t1][3], ah0, ah1, ah2, ah3, bh2, bh3);\
        mma_bf16(acc[t0][0], acc[t0][1], acc[t0][2], acc[t0][3], ah0, ah1, ah2, ah3, bl0, bl1);\
        mma_bf16(acc[t1][0], acc[t1][1], acc[t1][2], acc[t1][3], ah0, ah1, ah2, ah3, bl2, bl3);\
        mma_bf16(acc[t0][0], acc[t0][1], acc[t0][2], acc[t0][3], al0, al1, al2, al3, bh0, bh1);\
        mma_bf16(acc[t1][0], acc[t1][1], acc[t1][2], acc[t1][3], al0, al1, al2, al3, bh2, bh3);\
    }

#define SPLIT_FRAGS(v00, v10, v01, v11)                                                        \
    uint32_t ah0, ah1, ah2, ah3, al0, al1, al2, al3;                                           \
    split2(v00, ah0, al0);                                                                     \
    split2(v10, ah1, al1);                                                                     \
    split2(v01, ah2, al2);                                                                     \
    split2(v11, ah3, al3);

// ---------------- K0: init accumulators ----------------
__global__ void init_kernel(float* __restrict__ out) {
    int stride = gridDim.x * blockDim.x;
    int i0 = blockIdx.x * blockDim.x + threadIdx.x;
    for (int i = i0; i < N_ITEMS * DIM; i += stride) d_ft[i] = 0.0f;
    for (int i = i0; i < N_TGT * DIM;  i += stride) out[i]  = 0.0f;
    for (int i = i0; i < N_ITEMS;      i += stride) { d_z[i] = 0.0f; d_menc[i] = (int)0x80000000; }
}

// ---------------- prep: bf16 hi/lo transposed tiles of W_q (both halves) ----------------
__global__ void prep_wq_kernel(const float* __restrict__ W_q) {
    int i = blockIdx.x * blockDim.x + threadIdx.x;
    if (i >= 2 * DIM * DIM) return;
    int half = i >> 14;
    int j = i & 16383;
    int n = j >> 7, k = j & 127;
    float w = W_q[(size_t)(half * DIM + k) * DIM + n];
    __nv_bfloat16 hi = __float2bfloat16(w);
    __nv_bfloat16 lo = __float2bfloat16(w - __bfloat162float(hi));
    uint32_t off = (uint32_t)n * ROWB + k * 2;
    unsigned char* bh = half ? d_Bh2 : d_BhT;
    unsigned char* bl = half ? d_Bl2 : d_BlT;
    *(__nv_bfloat16*)(bh + off) = hi;
    *(__nv_bfloat16*)(bl + off) = lo;
}

// ---------------- prep: bf16 hi/lo transposed tiles of W_r (both halves) ----------------
__global__ void prep_wr_kernel(const float* __restrict__ W_r) {
    int i = blockIdx.x * blockDim.x + threadIdx.x;
    if (i >= 2 * DIM * DIM) return;
    int half = i >> 14;
    int j = i & 16383;
    int n = j >> 7, k = j & 127;
    float w = W_r[(size_t)(half * DIM + k) * DIM + n];
    __nv_bfloat16 hi = __float2bfloat16(w);
    __nv_bfloat16 lo = __float2bfloat16(w - __bfloat162float(hi));
    uint32_t off = (uint32_t)n * ROWB + k * 2;
    unsigned char* bh = half ? d_BhR1 : d_BhR0;
    unsigned char* bl = half ? d_BlR1 : d_BlR0;
    *(__nv_bfloat16*)(bh + off) = hi;
    *(__nv_bfloat16*)(bl + off) = lo;
}

// ---------------- K1: per-edge logit + segment max (4 edges per warp) ----------------
__global__ __launch_bounds__(256) void edge1_kernel(
    const float* __restrict__ h_v, const float* __restrict__ h_d,
    const float* __restrict__ W_pi, const float* __restrict__ W_M,
    const int* __restrict__ src1, const int* __restrict__ dst1)
{
    int warp = blockIdx.x * 8 + (threadIdx.x >> 5);
    int lane = threadIdx.x & 31;
    int e0 = warp * 4;
    float4 p  = ((const float4*)W_pi)[lane];
    float4 ma = ((const float4*)W_M)[lane];
    float4 mb = ((const float4*)(W_M + DIM))[lane];
    int s[4], d[4];
    #pragma unroll
    for (int i = 0; i < 4; i++) { s[i] = src1[e0 + i]; d[i] = dst1[e0 + i]; }
    float4 a[4], b[4], hh[4];
    #pragma unroll
    for (int i = 0; i < 4; i++) {
        a[i]  = ((const float4*)(h_v + (size_t)s[i] * DIM))[lane];
        b[i]  = ((const float4*)(h_v + (size_t)d[i] * DIM))[lane];
        hh[i] = __ldcs(((const float4*)(h_d + (size_t)(e0 + i) * DIM)) + lane);
    }
    float ev[4], mv[4];
    #pragma unroll
    for (int i = 0; i < 4; i++) {
        float4 uv = make_float4(a[i].x*b[i].x, a[i].y*b[i].y, a[i].z*b[i].z, a[i].w*b[i].w);
        ev[i] = uv.x*hh[i].x*p.x + uv.y*hh[i].y*p.y + uv.z*hh[i].z*p.z + uv.w*hh[i].w*p.w;
        mv[i] = uv.x*ma.x + uv.y*ma.y + uv.z*ma.z + uv.w*ma.w
              + hh[i].x*mb.x + hh[i].y*mb.y + hh[i].z*mb.z + hh[i].w*mb.w;
    }
    #pragma unroll
    for (int o = 16; o; o >>= 1) {
        #pragma unroll
        for (int i = 0; i < 4; i++) {
            ev[i] += __shfl_xor_sync(0xffffffffu, ev[i], o);
            mv[i] += __shfl_xor_sync(0xffffffffu, mv[i], o);
        }
    }
    if (lane == 0) {
        #pragma unroll
        for (int i = 0; i < 4; i++) {
            float e = ev[i] * (1.0f / (1.0f + expf(-mv[i])));
            d_e1[e0 + i] = e;
            atomicMax(&d_menc[d[i]], fenc(e));
        }
    }
}

// ---------------- K2: exp + segment sum (thread per edge) ----------------
__global__ void edge1_softmax_kernel(const int* __restrict__ dst1) {
    int e = blockIdx.x * blockDim.x + threadIdx.x;
    if (e >= E1N) return;
    int d = dst1[e];
    float m = fdec(d_menc[d]);
    float v = expf(d_e1[e] - m);
    d_ex[e] = v;
    atomicAdd(&d_z[d], v);
}

// ---------------- K3: normalize + aggregate ft (4 edges per warp) ----------------
__global__ __launch_bounds__(256) void edge1_agg_kernel(
    const float* __restrict__ h_v,
    const int* __restrict__ src1, const int* __restrict__ dst1)
{
    int warp = blockIdx.x * 8 + (threadIdx.x >> 5);
    int lane = threadIdx.x & 31;
    int e0 = warp * 4;
    int s[4], d[4];
    #pragma unroll
    for (int i = 0; i < 4; i++) { s[i] = src1[e0 + i]; d[i] = dst1[e0 + i]; }
    float a[4];
    #pragma unroll
    for (int i = 0; i < 4; i++) a[i] = d_ex[e0 + i] / d_z[d[i]];
    float4 v[4];
    #pragma unroll
    for (int i = 0; i < 4; i++) v[i] = ((const float4*)(h_v + (size_t)s[i] * DIM))[lane];
    #pragma unroll
    for (int i = 0; i < 4; i++) {
        v[i].x *= a[i]; v[i].y *= a[i]; v[i].z *= a[i]; v[i].w *= a[i];
        red_add_v4(d_ft + (size_t)d[i] * DIM + lane * 4, v[i]);
    }
}

// ---------------- K4: g = ft @ W_q[:128]  (mma.sync bf16-split, pipelined A) ----------------
#define SMG_TOTAL (2 * BTILE)
__global__ __launch_bounds__(256, 2) void gemm_g_mma() {
    extern __shared__ __align__(16) char smem[];
    uint32_t sb = smem_to_u32(smem);
    int tid = threadIdx.x;
    int w = tid >> 5;
    int lane = tid & 31;

    {
        const float4* gh = (const float4*)d_BhT;
        const float4* gl = (const float4*)d_BlT;
        float4* sh = (float4*)smem;
        float4* sl = (float4*)(smem + BTILE);
        for (int i = tid; i < BTILE / 16; i += 256) { sh[i] = gh[i]; sl[i] = gl[i]; }
    }
    __syncthreads();

    float acc[16][4];
    #pragma unroll
    for (int t = 0; t < 16; t++)
        #pragma unroll
        for (int j = 0; j < 4; j++) acc[t][j] = 0.0f;

    int qi = lane & 7;
    int quad = lane >> 3;
    uint32_t b_lane = (uint32_t)(qi + ((quad >= 2) ? 8 : 0)) * ROWB + ((quad & 1) ? 16 : 0);
    uint32_t bh_base = sb + b_lane;
    uint32_t bl_base = sb + BTILE + b_lane;

    int row0 = blockIdx.x * 128 + w * 16 + (lane >> 2);
    int row1 = row0 + 8;
    int r0c = (row0 < N_ITEMS) ? row0 : (N_ITEMS - 1);
    int r1c = (row1 < N_ITEMS) ? row1 : (N_ITEMS - 1);
    const float* pa = d_ft + (size_t)r0c * DIM;
    const float* pb = d_ft + (size_t)r1c * DIM;
    int c0 = (lane & 3) * 2;

    float2 n00 = *(const float2*)(pa + c0);
    float2 n10 = *(const float2*)(pb + c0);
    float2 n01 = *(const float2*)(pa + c0 + 8);
    float2 n11 = *(const float2*)(pb + c0 + 8);
    #pragma unroll
    for (int k16 = 0; k16 < 8; k16++) {
        float2 v00 = n00, v10 = n10, v01 = n01, v11 = n11;
        if (k16 < 7) {
            int kb = (k16 + 1) * 16 + c0;
            n00 = *(const float2*)(pa + kb);
            n10 = *(const float2*)(pb + kb);
            n01 = *(const float2*)(pa + kb + 8);
            n11 = *(const float2*)(pb + kb + 8);
        }
        SPLIT_FRAGS(v00, v10, v01, v11);
        MMA_STRIP((uint32_t)k16 * 32);
    }

    #pragma unroll
    for (int t = 0; t < 16; t++) {
        int n = t * 8 + c0;
        if (row0 < N_ITEMS) *(float2*)&d_g[(size_t)row0 * DIM + n] = make_float2(acc[t][0], acc[t][1]);
        if (row1 < N_ITEMS) *(float2*)&d_g[(size_t)row1 * DIM + n] = make_float2(acc[t][2], acc[t][3]);
    }
}

// ---------------- K5: f = concat(h_t, ft[last]) @ W_r  (mma.sync, 2-phase K) ----------------
__global__ __launch_bounds__(256, 2) void gemm_f_mma(
    const float* __restrict__ h_t, const int* __restrict__ last_idx)
{
    extern __shared__ __align__(16) char smem[];
    uint32_t sb = smem_to_u32(smem);
    int tid = threadIdx.x;
    int w = tid >> 5;
    int lane = tid & 31;

    float acc[16][4];
    #pragma unroll
    for (int t = 0; t < 16; t++)
        #pragma unroll
        for (int j = 0; j < 4; j++) acc[t][j] = 0.0f;

    int qi = lane & 7;
    int quad = lane >> 3;
    uint32_t b_lane = (uint32_t)(qi + ((quad >= 2) ? 8 : 0)) * ROWB + ((quad & 1) ? 16 : 0);
    uint32_t bh_base = sb + b_lane;
    uint32_t bl_base = sb + BTILE + b_lane;

    int row0 = blockIdx.x * 128 + w * 16 + (lane >> 2);
    int row1 = row0 + 8;
    int r0c = (row0 < N_TGT) ? row0 : (N_TGT - 1);
    int r1c = (row1 < N_TGT) ? row1 : (N_TGT - 1);
    int c0 = (lane & 3) * 2;

    // phase 0: B = W_r[0:128]^T, A = h_t
    {
        const float4* gh = (const float4*)d_BhR0;
        const float4* gl = (const float4*)d_BlR0;
        float4* sh = (float4*)smem;
        float4* sl = (float4*)(smem + BTILE);
        for (int i = tid; i < BTILE / 16; i += 256) { sh[i] = gh[i]; sl[i] = gl[i]; }
    }
    __syncthreads();
    {
        const float* pa = h_t + (size_t)r0c * DIM;
        const float* pb = h_t + (size_t)r1c * DIM;
        #pragma unroll
        for (int k16 = 0; k16 < 8; k16++) {
            float2 v00 = *(const float2*)(pa + k16 * 16 + c0);
            float2 v10 = *(const float2*)(pb + k16 * 16 + c0);
            float2 v01 = *(const float2*)(pa + k16 * 16 + c0 + 8);
            float2 v11 = *(const float2*)(pb + k16 * 16 + c0 + 8);
            SPLIT_FRAGS(v00, v10, v01, v11);
            MMA_STRIP((uint32_t)k16 * 32);
        }
    }
    __syncthreads();

    // phase 1: B = W_r[128:256]^T, A = ft[last_idx[row/4]]
    {
        const float4* gh = (const float4*)d_BhR1;
        const float4* gl = (const float4*)d_BlR1;
        float4* sh = (float4*)smem;
        float4* sl = (float4*)(smem + BTILE);
        for (int i = tid; i < BTILE / 16; i += 256) { sh[i] = gh[i]; sl[i] = gl[i]; }
    }
    __syncthreads();
    {
        const float* pa = d_ft + (size_t)last_idx[r0c >> 2] * DIM;
        const float* pb = d_ft + (size_t)last_idx[r1c >> 2] * DIM;
        #pragma unroll
        for (int k16 = 0; k16 < 8; k16++) {
            float2 v00 = *(const float2*)(pa + k16 * 16 + c0);
            float2 v10 = *(const float2*)(pb + k16 * 16 + c0);
            float2 v01 = *(const float2*)(pa + k16 * 16 + c0 + 8);
            float2 v11 = *(const float2*)(pb + k16 * 16 + c0 + 8);
            SPLIT_FRAGS(v00, v10, v01, v11);
            MMA_STRIP((uint32_t)k16 * 32);
        }
    }

    #pragma unroll
    for (int t = 0; t < 16; t++) {
        int n = t * 8 + c0;
        if (row0 < N_TGT) *(float2*)&d_f[(size_t)row0 * DIM + n] = make_float2(acc[t][0], acc[t][1]);
        if (row1 < N_TGT) *(float2*)&d_f[(size_t)row1 * DIM + n] = make_float2(acc[t][2], acc[t][3]);
    }
}

// ---------------- K6a: edge2 GEMM + tanh rowdot -> d_s  (R7 mainloop, no scatter) ----------------
#define SM_BH   0
#define SM_BL   BTILE
#define SM_SRC  (2 * BTILE)
#define SM_DST  (SM_SRC + 512)
#define SM_TOTAL (SM_DST + 512)

__global__ __launch_bounds__(256, 2)
void edge2_gemm_kernel(
    const float* __restrict__ h_p,
    const int* __restrict__ src2, const int* __restrict__ dst2)
{
    extern __shared__ __align__(16) char smem[];
    uint32_t sb = smem_to_u32(smem);
    int tid = threadIdx.x;
    int w = tid >> 5;
    int lane = tid & 31;
    int eb = blockIdx.x * 128;

    int* ssrc = (int*)(smem + SM_SRC);
    int* sdst = (int*)(smem + SM_DST);

    if (tid < 128) { ssrc[tid] = src2[eb + tid]; sdst[tid] = dst2[eb + tid]; }

    {
        const float4* gh = (const float4*)d_Bh2;
        const float4* gl = (const float4*)d_Bl2;
        float4* sh = (float4*)(smem + SM_BH);
        float4* sl = (float4*)(smem + SM_BL);
        for (int i = tid; i < BTILE / 16; i += 256) { sh[i] = gh[i]; sl[i] = gl[i]; }
    }
    __syncthreads();

    float acc[16][4];
    #pragma unroll
    for (int t = 0; t < 16; t++)
        #pragma unroll
        for (int j = 0; j < 4; j++) acc[t][j] = 0.0f;

    int qi = lane & 7;
    int quad = lane >> 3;
    uint32_t b_lane = (uint32_t)(qi + ((quad >= 2) ? 8 : 0)) * ROWB + ((quad & 1) ? 16 : 0);
    uint32_t bh_base = sb + SM_BH + b_lane;
    uint32_t bl_base = sb + SM_BL + b_lane;

    const float* pa = h_p + (size_t)(eb + w * 16 + (lane >> 2)) * DIM;
    const float* pb = pa + 8 * DIM;
    int c0 = (lane & 3) * 2;

    float2 n00 = *(const float2*)(pa + c0);
    float2 n10 = *(const float2*)(pb + c0);
    float2 n01 = *(const float2*)(pa + c0 + 8);
    float2 n11 = *(const float2*)(pb + c0 + 8);
    #pragma unroll
    for (int k16 = 0; k16 < 8; k16++) {
        float2 v00 = n00, v10 = n10, v01 = n01, v11 = n11;
        if (k16 < 7) {
            int kb = (k16 + 1) * 16 + c0;
            n00 = *(const float2*)(pa + kb);
            n10 = *(const float2*)(pb + kb);
            n01 = *(const float2*)(pa + kb + 8);
            n11 = *(const float2*)(pb + kb + 8);
        }
        SPLIT_FRAGS(v00, v10, v01, v11);
        MMA_STRIP((uint32_t)k16 * 32);
    }

    // epilogue: e2 = tanh(acc + g[src]); s = sum(e2 * f[dst]) -> d_s
    {
        int r0 = w * 16 + (lane >> 2);
        int r1 = r0 + 8;
        const float* g0p = d_g + (size_t)ssrc[r0] * DIM;
        const float* f0p = d_f + (size_t)sdst[r0] * DIM;
        const float* g1p = d_g + (size_t)ssrc[r1] * DIM;
        const float* f1p = d_f + (size_t)sdst[r1] * DIM;
        float s0 = 0.0f, s1 = 0.0f;
        #pragma unroll
        for (int t = 0; t < 16; t++) {
            int n = t * 8 + c0;
            float2 ga = *(const float2*)(g0p + n);
            float2 fa = *(const float2*)(f0p + n);
            float2 gb = *(const float2*)(g1p + n);
            float2 fb = *(const float2*)(f1p + n);
            s0 += tanh_fast(acc[t][0] + ga.x) * fa.x + tanh_fast(acc[t][1] + ga.y) * fa.y;
            s1 += tanh_fast(acc[t][2] + gb.x) * fb.x + tanh_fast(acc[t][3] + gb.y) * fb.y;
        }
        s0 += __shfl_xor_sync(0xffffffffu, s0, 1);
        s0 += __shfl_xor_sync(0xffffffffu, s0, 2);
        s1 += __shfl_xor_sync(0xffffffffu, s1, 1);
        s1 += __shfl_xor_sync(0xffffffffu, s1, 2);
        if ((lane & 3) == 0) { d_s[eb + r0] = s0; d_s[eb + r1] = s1; }
    }
}

// ---------------- K6b: scatter out[dst2[e]] += ft[src2[e]] * s[e]  (agg pattern, 4/warp) ----------------
__global__ __launch_bounds__(256) void edge2_scatter_kernel(
    const int* __restrict__ src2, const int* __restrict__ dst2,
    float* __restrict__ out)
{
    int warp = blockIdx.x * 8 + (threadIdx.x >> 5);
    int lane = threadIdx.x & 31;
    int e0 = warp * 4;
    int s[4], d[4];
    #pragma unroll
    for (int i = 0; i < 4; i++) { s[i] = src2[e0 + i]; d[i] = dst2[e0 + i]; }
    float sv[4];
    #pragma unroll
    for (int i = 0; i < 4; i++) sv[i] = d_s[e0 + i];
    float4 v[4];
    #pragma unroll
    for (int i = 0; i < 4; i++) v[i] = ((const float4*)(d_ft + (size_t)s[i] * DIM))[lane];
    #pragma unroll
    for (int i = 0; i < 4; i++) {
        v[i].x *= sv[i]; v[i].y *= sv[i]; v[i].z *= sv[i]; v[i].w *= sv[i];
        red_add_v4(out + (size_t)d[i] * DIM + lane * 4, v[i]);
    }
}

// ---------------- launcher ----------------
extern "C" void kernel_launch(void* const* d_in, const int* in_sizes, int n_in,
                              void* d_out, int out_size) {
    const float* h_v  = (const float*)d_in[0];
    const float* h_d  = (const float*)d_in[1];
    const float* h_p  = (const float*)d_in[2];
    const float* h_t  = (const float*)d_in[3];
    const float* W_pi = (const float*)d_in[4];
    const float* W_M  = (const float*)d_in[5];
    const float* W_q  = (const float*)d_in[6];
    const float* W_r  = (const float*)d_in[7];
    const int* src1 = (const int*)d_in[8];
    const int* dst1 = (const int*)d_in[9];
    const int* src2 = (const int*)d_in[10];
    const int* dst2 = (const int*)d_in[11];
    const int* last_idx = (const int*)d_in[12];
    float* out = (float*)d_out;

    cudaFuncSetAttribute(edge2_gemm_kernel, cudaFuncAttributeMaxDynamicSharedMemorySize, SM_TOTAL);
    cudaFuncSetAttribute(gemm_g_mma, cudaFuncAttributeMaxDynamicSharedMemorySize, SMG_TOTAL);
    cudaFuncSetAttribute(gemm_f_mma, cudaFuncAttributeMaxDynamicSharedMemorySize, SMG_TOTAL);

    init_kernel<<<2048, 256>>>(out);                          // 0
    prep_wq_kernel<<<(2 * DIM * DIM + 255) / 256, 256>>>(W_q); // 1
    prep_wr_kernel<<<(2 * DIM * DIM + 255) / 256, 256>>>(W_r); // 2
    edge1_kernel<<<E1N / 32, 256>>>(h_v, h_d, W_pi, W_M, src1, dst1); // 3 <- profiled
    edge1_softmax_kernel<<<(E1N + 255) / 256, 256>>>(dst1);   // 4
    edge1_agg_kernel<<<E1N / 32, 256>>>(h_v, src1, dst1);     // 5
    gemm_g_mma<<<(N_ITEMS + 127) / 128, 256, SMG_TOTAL>>>();  // 6
    gemm_f_mma<<<(N_TGT + 127) / 128, 256, SMG_TOTAL>>>(h_t, last_idx); // 7
    edge2_gemm_kernel<<<E2N / 128, 256, SM_TOTAL>>>(h_p, src2, dst2);   // 8
    edge2_scatter_kernel<<<E2N / 32, 256>>>(src2, dst2, out); // 9
}